// round 11
// baseline (speedup 1.0000x reference)
#include <cuda_runtime.h>

#define N_NODES  100000
#define N_EDGES  2500000
#define N_GRAPHS 512
#define IN_DIM   14
#define HID      32

#define CONV_TPB    512
#define CONV_BLOCKS 592     // 9472 warps, grid-stride over nodes

// ---------------- device scratch ----------------
__device__ float4 d_x4[N_NODES * 4];        // x padded 14 -> 16 floats
__device__ float4 d_h0v[N_NODES * 8];
__device__ float4 d_h1v[N_NODES * 8];
__device__ float4 d_pool4[N_GRAPHS * 8];
__device__ int    d_deg[N_NODES];           // degree, then fill cursor
__device__ int    d_off[N_NODES + 1];       // CSR row offsets (by dst)
__device__ int    d_csrc[N_EDGES];          // CSR column = src node of each edge

__device__ __forceinline__ void red_add_v4(float4* p, float4 v) {
    asm volatile("red.global.add.v4.f32 [%0], {%1,%2,%3,%4};"
                 :: "l"(p), "f"(v.x), "f"(v.y), "f"(v.z), "f"(v.w)
                 : "memory");
}

// ---------------- prep: pad x, zero deg + pool ----------------
__global__ void k_prep(const float* __restrict__ x) {
    int i = blockIdx.x * blockDim.x + threadIdx.x;
    if (i < N_NODES) {
        float buf[16];
        #pragma unroll
        for (int k = 0; k < IN_DIM; k++) buf[k] = x[i * IN_DIM + k];
        buf[14] = 0.0f; buf[15] = 0.0f;
        #pragma unroll
        for (int k = 0; k < 4; k++)
            d_x4[i * 4 + k] = make_float4(buf[4*k], buf[4*k+1], buf[4*k+2], buf[4*k+3]);
        d_deg[i] = 0;
    }
    if (i < N_GRAPHS * 8) d_pool4[i] = make_float4(0.f, 0.f, 0.f, 0.f);
}

// ---------------- CSR build ----------------
__global__ void k_hist(const int* __restrict__ ei) {
    int i = blockIdx.x * blockDim.x + threadIdx.x;
    const int4* dst4 = (const int4*)(ei + N_EDGES);
    if (i < N_EDGES / 4) {
        int4 d = dst4[i];
        atomicAdd(&d_deg[d.x], 1);
        atomicAdd(&d_deg[d.y], 1);
        atomicAdd(&d_deg[d.z], 1);
        atomicAdd(&d_deg[d.w], 1);
    }
}

__global__ void k_scan() {
    const int C = (N_NODES + 1023) / 1024;  // 98
    __shared__ int sPart[1024];
    int t = threadIdx.x;
    int start = t * C;
    int sum = 0;
    for (int i = 0; i < C; i++) {
        int idx = start + i;
        if (idx < N_NODES) sum += d_deg[idx];
    }
    sPart[t] = sum;
    __syncthreads();
    for (int off = 1; off < 1024; off <<= 1) {
        int v = (t >= off) ? sPart[t - off] : 0;
        __syncthreads();
        sPart[t] += v;
        __syncthreads();
    }
    int run = (t == 0) ? 0 : sPart[t - 1];
    for (int i = 0; i < C; i++) {
        int idx = start + i;
        if (idx < N_NODES) {
            int d = d_deg[idx];
            d_off[idx] = run;
            d_deg[idx] = run;   // becomes fill cursor
            run += d;
        }
    }
    if (t == 0) d_off[N_NODES] = N_EDGES;
}

__global__ void k_fill(const int* __restrict__ ei) {
    int i = blockIdx.x * blockDim.x + threadIdx.x;
    if (i < N_EDGES) {
        int s = ei[i], d = ei[N_EDGES + i];
        int pos = atomicAdd(&d_deg[d], 1);
        d_csrc[pos] = s;
    }
}

// ---------------- layer 1: 8-edges/LDG.128 gather + shfl/register epilogue ---------
// 4 lanes per edge: grp = lane>>2 (edge within batch), sub = lane&3 (float4 index)
__global__ void __launch_bounds__(CONV_TPB) k_conv1(const float* __restrict__ Wrel,
                                                    const float* __restrict__ brel,
                                                    const float* __restrict__ Wroot) {
    __shared__ float2 sWW[IN_DIM * HID];    // (Wrel[k][j], Wroot[k][j])
    for (int k = threadIdx.x; k < IN_DIM * HID; k += blockDim.x)
        sWW[k] = make_float2(Wrel[k], Wroot[k]);
    __syncthreads();

    const float4* xp4 = d_x4;
    const float*  xp  = (const float*)d_x4;
    float* h0 = (float*)d_h0v;
    int lane = threadIdx.x & 31, w = threadIdx.x >> 5;
    float bias = brel[lane];
    int warpId = blockIdx.x * (CONV_TPB / 32) + w;
    int nWarps = gridDim.x * (CONV_TPB / 32);
    int grp = lane >> 2;     // 0..7: edge within 8-edge batch
    int sub = lane & 3;      // 0..3: float4 within 16-float row

    for (int n = warpId; n < N_NODES; n += nWarps) {
        int beg = d_off[n], end = d_off[n + 1];
        float4 acc0 = make_float4(0.f,0.f,0.f,0.f);
        float4 acc1 = make_float4(0.f,0.f,0.f,0.f);
        for (int base = beg; base < end; base += 32) {
            int cnt = end - base; if (cnt > 32) cnt = 32;
            int sidx = (base + lane < end) ? d_csrc[base + lane] : 0;
            int j = 0;
            for (; j + 16 <= cnt; j += 16) {
                int sa = __shfl_sync(0xffffffffu, sidx, j + grp);
                int sb_ = __shfl_sync(0xffffffffu, sidx, j + 8 + grp);
                float4 va = xp4[sa * 4 + sub];
                float4 vb = xp4[sb_ * 4 + sub];
                acc0.x += va.x; acc0.y += va.y; acc0.z += va.z; acc0.w += va.w;
                acc1.x += vb.x; acc1.y += vb.y; acc1.z += vb.z; acc1.w += vb.w;
            }
            for (; j < cnt; j += 8) {
                int s = __shfl_sync(0xffffffffu, sidx, j + grp);
                if (j + grp < cnt) {
                    float4 v = xp4[s * 4 + sub];
                    acc0.x += v.x; acc0.y += v.y; acc0.z += v.z; acc0.w += v.w;
                }
            }
        }
        float4 acc = make_float4(acc0.x + acc1.x, acc0.y + acc1.y,
                                 acc0.z + acc1.z, acc0.w + acc1.w);
        // reduce across 8 edge-groups (lane bits 2..4): all lanes end with agg[4*sub..]
        #pragma unroll
        for (int d = 4; d <= 16; d <<= 1) {
            acc.x += __shfl_xor_sync(0xffffffffu, acc.x, d);
            acc.y += __shfl_xor_sync(0xffffffffu, acc.y, d);
            acc.z += __shfl_xor_sync(0xffffffffu, acc.z, d);
            acc.w += __shfl_xor_sync(0xffffffffu, acc.w, d);
        }
        float hs = xp[n * 16 + (lane & 15)];   // lane j holds x[n][j&15]

        float o = bias;
        float* accp = &acc.x;
        #pragma unroll
        for (int k = 0; k < IN_DIM; k++) {
            float2 wk = sWW[k * HID + lane];
            float ak = __shfl_sync(0xffffffffu, accp[k & 3], k >> 2);
            float hk = __shfl_sync(0xffffffffu, hs, k);
            o = fmaf(ak, wk.x, o);
            o = fmaf(hk, wk.y, o);
        }
        h0[n * HID + lane] = fmaxf(o, 0.0f);
    }
}

// ---------------- layers 2..5: 4-edges/LDG.128 gather + shfl/register epilogue -----
// 8 lanes per edge: grp = lane>>3 (edge within batch), sub = lane&7 (float4 index)
__global__ void __launch_bounds__(CONV_TPB) k_conv32(int src_is_h0,
                                                     const float* __restrict__ Wrel,
                                                     const float* __restrict__ brel,
                                                     const float* __restrict__ Wroot) {
    __shared__ float2 sWW[HID * HID];       // (Wrel[k][j], Wroot[k][j])
    for (int k = threadIdx.x; k < HID * HID; k += blockDim.x)
        sWW[k] = make_float2(Wrel[k], Wroot[k]);
    __syncthreads();

    const float4* hin4 = src_is_h0 ? d_h0v : d_h1v;
    const float*  hin  = (const float*)hin4;
    float*        hout = src_is_h0 ? (float*)d_h1v : (float*)d_h0v;

    int lane = threadIdx.x & 31, w = threadIdx.x >> 5;
    float bias = brel[lane];
    int warpId = blockIdx.x * (CONV_TPB / 32) + w;
    int nWarps = gridDim.x * (CONV_TPB / 32);
    int grp = lane >> 3;     // 0..3: edge within 4-edge batch
    int sub = lane & 7;      // 0..7: float4 within 32-float row

    for (int n = warpId; n < N_NODES; n += nWarps) {
        int beg = d_off[n], end = d_off[n + 1];
        float4 acc0 = make_float4(0.f,0.f,0.f,0.f);
        float4 acc1 = make_float4(0.f,0.f,0.f,0.f);
        for (int base = beg; base < end; base += 32) {
            int cnt = end - base; if (cnt > 32) cnt = 32;
            int sidx = (base + lane < end) ? d_csrc[base + lane] : 0;
            int j = 0;
            for (; j + 8 <= cnt; j += 8) {
                int sa = __shfl_sync(0xffffffffu, sidx, j + grp);
                int sb_ = __shfl_sync(0xffffffffu, sidx, j + 4 + grp);
                float4 va = hin4[sa * 8 + sub];
                float4 vb = hin4[sb_ * 8 + sub];
                acc0.x += va.x; acc0.y += va.y; acc0.z += va.z; acc0.w += va.w;
                acc1.x += vb.x; acc1.y += vb.y; acc1.z += vb.z; acc1.w += vb.w;
            }
            for (; j < cnt; j += 4) {
                int s = __shfl_sync(0xffffffffu, sidx, j + grp);
                if (j + grp < cnt) {
                    float4 v = hin4[s * 8 + sub];
                    acc0.x += v.x; acc0.y += v.y; acc0.z += v.z; acc0.w += v.w;
                }
            }
        }
        float4 acc = make_float4(acc0.x + acc1.x, acc0.y + acc1.y,
                                 acc0.z + acc1.z, acc0.w + acc1.w);
        // reduce across 4 edge-groups: all lanes end with agg[4*sub .. 4*sub+3]
        #pragma unroll
        for (int d = 8; d <= 16; d <<= 1) {
            acc.x += __shfl_xor_sync(0xffffffffu, acc.x, d);
            acc.y += __shfl_xor_sync(0xffffffffu, acc.y, d);
            acc.z += __shfl_xor_sync(0xffffffffu, acc.z, d);
            acc.w += __shfl_xor_sync(0xffffffffu, acc.w, d);
        }
        float hs = hin[n * HID + lane];        // lane j holds h[n][j]

        float o = bias;
        float* accp = &acc.x;
        #pragma unroll
        for (int k = 0; k < HID; k++) {
            float2 wk = sWW[k * HID + lane];
            float ak = __shfl_sync(0xffffffffu, accp[k & 3], k >> 2);
            float hk = __shfl_sync(0xffffffffu, hs, k);
            o = fmaf(ak, wk.x, o);
            o = fmaf(hk, wk.y, o);
        }
        hout[n * HID + lane] = fmaxf(o, 0.0f);
    }
}

// ---------------- sum-pool per graph ----------------
__global__ void k_pool(int src_is_h0, const int* __restrict__ batch) {
    int t = blockIdx.x * blockDim.x + threadIdx.x;
    if (t >= 8 * N_NODES) return;
    const float4* h = src_is_h0 ? d_h0v : d_h1v;
    int n = t >> 3, c = t & 7;
    int g = batch[n];
    float4 v = h[n * 8 + c];
    red_add_v4(&d_pool4[g * 8 + c], v);
}

// ---------------- MLP head + log_softmax ----------------
__global__ void k_head(const float* __restrict__ lin1w, const float* __restrict__ lin1b,
                       const float* __restrict__ lin2w, const float* __restrict__ lin2b,
                       float* __restrict__ out) {
    __shared__ float s1[HID * HID], sb1[HID], s2[HID * 2], sb2[2];
    for (int k = threadIdx.x; k < HID * HID; k += blockDim.x) s1[k] = lin1w[k];
    if (threadIdx.x < HID)     sb1[threadIdx.x] = lin1b[threadIdx.x];
    if (threadIdx.x < HID * 2) s2[threadIdx.x]  = lin2w[threadIdx.x];
    if (threadIdx.x < 2)       sb2[threadIdx.x] = lin2b[threadIdx.x];
    __syncthreads();

    int g = threadIdx.x;
    if (g >= N_GRAPHS) return;

    const float* pool = (const float*)d_pool4;
    float gr[HID];
    #pragma unroll
    for (int k = 0; k < HID; k++) gr[k] = pool[g * HID + k];

    float hid[HID];
    for (int j = 0; j < HID; j++) {
        float acc = sb1[j];
        #pragma unroll
        for (int k = 0; k < HID; k++) acc += gr[k] * s1[k * HID + j];
        hid[j] = fmaxf(acc, 0.0f);
    }
    float l0 = sb2[0], l1 = sb2[1];
    #pragma unroll
    for (int k = 0; k < HID; k++) {
        l0 += hid[k] * s2[k * 2 + 0];
        l1 += hid[k] * s2[k * 2 + 1];
    }
    float m   = fmaxf(l0, l1);
    float lse = m + logf(expf(l0 - m) + expf(l1 - m));
    out[g * 2 + 0] = l0 - lse;
    out[g * 2 + 1] = l1 - lse;
}

// ---------------- launch: inputs identified BY ELEMENT COUNT (order-agnostic) -------
extern "C" void kernel_launch(void* const* d_in, const int* in_sizes, int n_in,
                              void* d_out, int out_size) {
    const float *x = 0, *Wrel1 = 0, *brel1 = 0, *Wroot1 = 0;
    const float *Wrel = 0, *brel = 0, *Wroot = 0;
    const float *lin1w = 0, *lin1b = 0, *lin2w = 0, *lin2b = 0;
    const int *ei = 0, *batch = 0;

    for (int i = 0; i < n_in; i++) {
        int sz = in_sizes[i];
        const void* p = d_in[i];
        switch (sz) {
            case 1400000: x      = (const float*)p; break;
            case 5000000: ei     = (const int*)p; break;
            case 100000:  batch  = (const int*)p; break;
            case 448:     if (!Wrel1) Wrel1 = (const float*)p; else Wroot1 = (const float*)p; break;
            case 4096:    if (!Wrel)  Wrel  = (const float*)p; else Wroot  = (const float*)p; break;
            case 32:      if (!brel1) brel1 = (const float*)p; else lin1b  = (const float*)p; break;
            case 128:     brel   = (const float*)p; break;
            case 1024:    lin1w  = (const float*)p; break;
            case 64:      lin2w  = (const float*)p; break;
            case 2:       lin2b  = (const float*)p; break;
            default: break;
        }
    }
    float* out = (float*)d_out;

    const int TB = 256;

    // prep + CSR build
    k_prep<<<(N_NODES + TB - 1) / TB, TB>>>(x);
    k_hist<<<(N_EDGES / 4 + TB - 1) / TB, TB>>>(ei);
    k_scan<<<1, 1024>>>();
    k_fill<<<(N_EDGES + TB - 1) / TB, TB>>>(ei);

    // layer 1 -> h0
    k_conv1<<<CONV_BLOCKS, CONV_TPB>>>(Wrel1, brel1, Wroot1);

    // layers 2..5 : ping-pong h0 <-> h1
    int src_is_h0 = 1;
    for (int i = 0; i < 4; i++) {
        k_conv32<<<CONV_BLOCKS, CONV_TPB>>>(
            src_is_h0,
            Wrel  + i * HID * HID,
            brel  + i * HID,
            Wroot + i * HID * HID);
        src_is_h0 ^= 1;
    }

    // final h lives in h0
    k_pool<<<(8 * N_NODES + TB - 1) / TB, TB>>>(src_is_h0, batch);
    k_head<<<1, N_GRAPHS>>>(lin1w, lin1b, lin2w, lin2b, out);
}

// round 12
// speedup vs baseline: 1.2227x; 1.2227x over previous
#include <cuda_runtime.h>

#define N_NODES  100000
#define N_EDGES  2500000
#define N_GRAPHS 512
#define IN_DIM   14
#define HID      32

#define CONV_TPB    512
#define CONV_BLOCKS 592     // 9472 warps

// ---------------- device scratch ----------------
__device__ float4 d_x4[N_NODES * 4];        // x padded 14 -> 16 floats
__device__ float4 d_h0v[N_NODES * 8];
__device__ float4 d_h1v[N_NODES * 8];
__device__ float4 d_pool4[N_GRAPHS * 8];
__device__ int    d_deg[N_NODES];           // degree, then fill cursor
__device__ int    d_off[N_NODES + 1];       // CSR row offsets (by dst)
__device__ int    d_csrc[N_EDGES];          // CSR column = src node of each edge

__device__ __forceinline__ void red_add_v4(float4* p, float4 v) {
    asm volatile("red.global.add.v4.f32 [%0], {%1,%2,%3,%4};"
                 :: "l"(p), "f"(v.x), "f"(v.y), "f"(v.z), "f"(v.w)
                 : "memory");
}

// ---------------- prep: pad x, zero deg + pool ----------------
__global__ void k_prep(const float* __restrict__ x) {
    int i = blockIdx.x * blockDim.x + threadIdx.x;
    if (i < N_NODES) {
        float buf[16];
        #pragma unroll
        for (int k = 0; k < IN_DIM; k++) buf[k] = x[i * IN_DIM + k];
        buf[14] = 0.0f; buf[15] = 0.0f;
        #pragma unroll
        for (int k = 0; k < 4; k++)
            d_x4[i * 4 + k] = make_float4(buf[4*k], buf[4*k+1], buf[4*k+2], buf[4*k+3]);
        d_deg[i] = 0;
    }
    if (i < N_GRAPHS * 8) d_pool4[i] = make_float4(0.f, 0.f, 0.f, 0.f);
}

// ---------------- CSR build ----------------
__global__ void k_hist(const int* __restrict__ ei) {
    int i = blockIdx.x * blockDim.x + threadIdx.x;
    const int4* dst4 = (const int4*)(ei + N_EDGES);
    if (i < N_EDGES / 4) {
        int4 d = dst4[i];
        atomicAdd(&d_deg[d.x], 1);
        atomicAdd(&d_deg[d.y], 1);
        atomicAdd(&d_deg[d.z], 1);
        atomicAdd(&d_deg[d.w], 1);
    }
}

__global__ void k_scan() {
    const int C = (N_NODES + 1023) / 1024;  // 98
    __shared__ int sPart[1024];
    int t = threadIdx.x;
    int start = t * C;
    int sum = 0;
    for (int i = 0; i < C; i++) {
        int idx = start + i;
        if (idx < N_NODES) sum += d_deg[idx];
    }
    sPart[t] = sum;
    __syncthreads();
    for (int off = 1; off < 1024; off <<= 1) {
        int v = (t >= off) ? sPart[t - off] : 0;
        __syncthreads();
        sPart[t] += v;
        __syncthreads();
    }
    int run = (t == 0) ? 0 : sPart[t - 1];
    for (int i = 0; i < C; i++) {
        int idx = start + i;
        if (idx < N_NODES) {
            int d = d_deg[idx];
            d_off[idx] = run;
            d_deg[idx] = run;   // becomes fill cursor
            run += d;
        }
    }
    if (t == 0) d_off[N_NODES] = N_EDGES;
}

__global__ void k_fill(const int* __restrict__ ei) {
    int i = blockIdx.x * blockDim.x + threadIdx.x;
    if (i < N_EDGES) {
        int s = ei[i], d = ei[N_EDGES + i];
        int pos = atomicAdd(&d_deg[d], 1);
        d_csrc[pos] = s;
    }
}

// ---------------- layer 1: R10 gather + node-blocked (B=4) epilogue ----------------
__global__ void __launch_bounds__(CONV_TPB) k_conv1(const float* __restrict__ Wrel,
                                                    const float* __restrict__ brel,
                                                    const float* __restrict__ Wroot) {
    __shared__ float2 sWW[IN_DIM * HID];                 // (Wrel, Wroot) packed
    __shared__ __align__(16) float sAggT[16][16][4];     // [warp][k][node-in-block]
    __shared__ __align__(16) float sHinT[16][16][4];
    for (int k = threadIdx.x; k < IN_DIM * HID; k += blockDim.x)
        sWW[k] = make_float2(Wrel[k], Wroot[k]);
    __syncthreads();

    const float4* xp4 = d_x4;
    const float*  xp  = (const float*)d_x4;
    float* h0 = (float*)d_h0v;
    int lane = threadIdx.x & 31, w = threadIdx.x >> 5;
    float bias = brel[lane];
    int warpId = blockIdx.x * (CONV_TPB / 32) + w;
    int nWarps = gridDim.x * (CONV_TPB / 32);
    int grp = lane >> 2;     // 0..7: edge within 8-edge batch
    int sub = lane & 3;      // 0..3: float4 within 16-float row

    const int NGRP = N_NODES / 4;   // 25000, exact
    for (int ng = warpId; ng < NGRP; ng += nWarps) {
        int n0 = ng * 4;
        #pragma unroll
        for (int b = 0; b < 4; b++) {
            int n = n0 + b;
            int beg = d_off[n], end = d_off[n + 1];
            float4 acc0 = make_float4(0.f,0.f,0.f,0.f);
            float4 acc1 = make_float4(0.f,0.f,0.f,0.f);
            for (int base = beg; base < end; base += 32) {
                int cnt = end - base; if (cnt > 32) cnt = 32;
                int sidx = (base + lane < end) ? d_csrc[base + lane] : 0;
                int j = 0;
                for (; j + 16 <= cnt; j += 16) {
                    int sa = __shfl_sync(0xffffffffu, sidx, j + grp);
                    int sb_ = __shfl_sync(0xffffffffu, sidx, j + 8 + grp);
                    float4 va = xp4[sa * 4 + sub];
                    float4 vb = xp4[sb_ * 4 + sub];
                    acc0.x += va.x; acc0.y += va.y; acc0.z += va.z; acc0.w += va.w;
                    acc1.x += vb.x; acc1.y += vb.y; acc1.z += vb.z; acc1.w += vb.w;
                }
                for (; j < cnt; j += 8) {
                    int s = __shfl_sync(0xffffffffu, sidx, j + grp);
                    if (j + grp < cnt) {
                        float4 v = xp4[s * 4 + sub];
                        acc0.x += v.x; acc0.y += v.y; acc0.z += v.z; acc0.w += v.w;
                    }
                }
            }
            float4 acc = make_float4(acc0.x + acc1.x, acc0.y + acc1.y,
                                     acc0.z + acc1.z, acc0.w + acc1.w);
            #pragma unroll
            for (int d = 4; d <= 16; d <<= 1) {
                acc.x += __shfl_xor_sync(0xffffffffu, acc.x, d);
                acc.y += __shfl_xor_sync(0xffffffffu, acc.y, d);
                acc.z += __shfl_xor_sync(0xffffffffu, acc.z, d);
                acc.w += __shfl_xor_sync(0xffffffffu, acc.w, d);
            }
            if (lane < 4) {                       // lanes 0..3 cover sub 0..3
                sAggT[w][4*lane+0][b] = acc.x;
                sAggT[w][4*lane+1][b] = acc.y;
                sAggT[w][4*lane+2][b] = acc.z;
                sAggT[w][4*lane+3][b] = acc.w;
            }
            if (lane < 16) sHinT[w][lane][b] = xp[n * 16 + lane];
        }
        __syncwarp();

        const float4* aggv = (const float4*)&sAggT[w][0][0];
        const float4* hinv = (const float4*)&sHinT[w][0][0];
        float o0 = bias, o1 = bias, o2 = bias, o3 = bias;
        #pragma unroll
        for (int k = 0; k < IN_DIM; k++) {
            float2 wk = sWW[k * HID + lane];
            float4 av = aggv[k];
            float4 hv = hinv[k];
            o0 = fmaf(av.x, wk.x, fmaf(hv.x, wk.y, o0));
            o1 = fmaf(av.y, wk.x, fmaf(hv.y, wk.y, o1));
            o2 = fmaf(av.z, wk.x, fmaf(hv.z, wk.y, o2));
            o3 = fmaf(av.w, wk.x, fmaf(hv.w, wk.y, o3));
        }
        h0[(n0+0) * HID + lane] = fmaxf(o0, 0.0f);
        h0[(n0+1) * HID + lane] = fmaxf(o1, 0.0f);
        h0[(n0+2) * HID + lane] = fmaxf(o2, 0.0f);
        h0[(n0+3) * HID + lane] = fmaxf(o3, 0.0f);
        __syncwarp();
    }
}

// ---------------- layers 2..5: R10 gather + node-blocked (B=4) epilogue ------------
__global__ void __launch_bounds__(CONV_TPB) k_conv32(int src_is_h0,
                                                     const float* __restrict__ Wrel,
                                                     const float* __restrict__ brel,
                                                     const float* __restrict__ Wroot) {
    __shared__ float2 sWW[HID * HID];                    // 8 KB
    __shared__ __align__(16) float sAggT[16][HID][4];    // 8 KB
    __shared__ __align__(16) float sHinT[16][HID][4];    // 8 KB
    for (int k = threadIdx.x; k < HID * HID; k += blockDim.x)
        sWW[k] = make_float2(Wrel[k], Wroot[k]);
    __syncthreads();

    const float4* hin4 = src_is_h0 ? d_h0v : d_h1v;
    const float*  hin  = (const float*)hin4;
    float*        hout = src_is_h0 ? (float*)d_h1v : (float*)d_h0v;

    int lane = threadIdx.x & 31, w = threadIdx.x >> 5;
    float bias = brel[lane];
    int warpId = blockIdx.x * (CONV_TPB / 32) + w;
    int nWarps = gridDim.x * (CONV_TPB / 32);
    int grp = lane >> 3;     // 0..3: edge within 4-edge batch
    int sub = lane & 7;      // 0..7: float4 within 32-float row

    const int NGRP = N_NODES / 4;   // 25000, exact
    for (int ng = warpId; ng < NGRP; ng += nWarps) {
        int n0 = ng * 4;
        #pragma unroll
        for (int b = 0; b < 4; b++) {
            int n = n0 + b;
            int beg = d_off[n], end = d_off[n + 1];
            float4 acc0 = make_float4(0.f,0.f,0.f,0.f);
            float4 acc1 = make_float4(0.f,0.f,0.f,0.f);
            for (int base = beg; base < end; base += 32) {
                int cnt = end - base; if (cnt > 32) cnt = 32;
                int sidx = (base + lane < end) ? d_csrc[base + lane] : 0;
                int j = 0;
                for (; j + 8 <= cnt; j += 8) {
                    int sa = __shfl_sync(0xffffffffu, sidx, j + grp);
                    int sb_ = __shfl_sync(0xffffffffu, sidx, j + 4 + grp);
                    float4 va = hin4[sa * 8 + sub];
                    float4 vb = hin4[sb_ * 8 + sub];
                    acc0.x += va.x; acc0.y += va.y; acc0.z += va.z; acc0.w += va.w;
                    acc1.x += vb.x; acc1.y += vb.y; acc1.z += vb.z; acc1.w += vb.w;
                }
                for (; j < cnt; j += 4) {
                    int s = __shfl_sync(0xffffffffu, sidx, j + grp);
                    if (j + grp < cnt) {
                        float4 v = hin4[s * 8 + sub];
                        acc0.x += v.x; acc0.y += v.y; acc0.z += v.z; acc0.w += v.w;
                    }
                }
            }
            float4 acc = make_float4(acc0.x + acc1.x, acc0.y + acc1.y,
                                     acc0.z + acc1.z, acc0.w + acc1.w);
            #pragma unroll
            for (int d = 8; d <= 16; d <<= 1) {
                acc.x += __shfl_xor_sync(0xffffffffu, acc.x, d);
                acc.y += __shfl_xor_sync(0xffffffffu, acc.y, d);
                acc.z += __shfl_xor_sync(0xffffffffu, acc.z, d);
                acc.w += __shfl_xor_sync(0xffffffffu, acc.w, d);
            }
            if (lane < 8) {                       // lanes 0..7 cover sub 0..7
                sAggT[w][4*lane+0][b] = acc.x;
                sAggT[w][4*lane+1][b] = acc.y;
                sAggT[w][4*lane+2][b] = acc.z;
                sAggT[w][4*lane+3][b] = acc.w;
            }
            sHinT[w][lane][b] = hin[n * HID + lane];
        }
        __syncwarp();

        const float4* aggv = (const float4*)&sAggT[w][0][0];
        const float4* hinv = (const float4*)&sHinT[w][0][0];
        float o0 = bias, o1 = bias, o2 = bias, o3 = bias;
        #pragma unroll
        for (int k = 0; k < HID; k++) {
            float2 wk = sWW[k * HID + lane];
            float4 av = aggv[k];
            float4 hv = hinv[k];
            o0 = fmaf(av.x, wk.x, fmaf(hv.x, wk.y, o0));
            o1 = fmaf(av.y, wk.x, fmaf(hv.y, wk.y, o1));
            o2 = fmaf(av.z, wk.x, fmaf(hv.z, wk.y, o2));
            o3 = fmaf(av.w, wk.x, fmaf(hv.w, wk.y, o3));
        }
        hout[(n0+0) * HID + lane] = fmaxf(o0, 0.0f);
        hout[(n0+1) * HID + lane] = fmaxf(o1, 0.0f);
        hout[(n0+2) * HID + lane] = fmaxf(o2, 0.0f);
        hout[(n0+3) * HID + lane] = fmaxf(o3, 0.0f);
        __syncwarp();
    }
}

// ---------------- sum-pool per graph ----------------
__global__ void k_pool(int src_is_h0, const int* __restrict__ batch) {
    int t = blockIdx.x * blockDim.x + threadIdx.x;
    if (t >= 8 * N_NODES) return;
    const float4* h = src_is_h0 ? d_h0v : d_h1v;
    int n = t >> 3, c = t & 7;
    int g = batch[n];
    float4 v = h[n * 8 + c];
    red_add_v4(&d_pool4[g * 8 + c], v);
}

// ---------------- MLP head + log_softmax ----------------
__global__ void k_head(const float* __restrict__ lin1w, const float* __restrict__ lin1b,
                       const float* __restrict__ lin2w, const float* __restrict__ lin2b,
                       float* __restrict__ out) {
    __shared__ float s1[HID * HID], sb1[HID], s2[HID * 2], sb2[2];
    for (int k = threadIdx.x; k < HID * HID; k += blockDim.x) s1[k] = lin1w[k];
    if (threadIdx.x < HID)     sb1[threadIdx.x] = lin1b[threadIdx.x];
    if (threadIdx.x < HID * 2) s2[threadIdx.x]  = lin2w[threadIdx.x];
    if (threadIdx.x < 2)       sb2[threadIdx.x] = lin2b[threadIdx.x];
    __syncthreads();

    int g = threadIdx.x;
    if (g >= N_GRAPHS) return;

    const float* pool = (const float*)d_pool4;
    float gr[HID];
    #pragma unroll
    for (int k = 0; k < HID; k++) gr[k] = pool[g * HID + k];

    float hid[HID];
    for (int j = 0; j < HID; j++) {
        float acc = sb1[j];
        #pragma unroll
        for (int k = 0; k < HID; k++) acc += gr[k] * s1[k * HID + j];
        hid[j] = fmaxf(acc, 0.0f);
    }
    float l0 = sb2[0], l1 = sb2[1];
    #pragma unroll
    for (int k = 0; k < HID; k++) {
        l0 += hid[k] * s2[k * 2 + 0];
        l1 += hid[k] * s2[k * 2 + 1];
    }
    float m   = fmaxf(l0, l1);
    float lse = m + logf(expf(l0 - m) + expf(l1 - m));
    out[g * 2 + 0] = l0 - lse;
    out[g * 2 + 1] = l1 - lse;
}

// ---------------- launch: inputs identified BY ELEMENT COUNT (order-agnostic) -------
extern "C" void kernel_launch(void* const* d_in, const int* in_sizes, int n_in,
                              void* d_out, int out_size) {
    const float *x = 0, *Wrel1 = 0, *brel1 = 0, *Wroot1 = 0;
    const float *Wrel = 0, *brel = 0, *Wroot = 0;
    const float *lin1w = 0, *lin1b = 0, *lin2w = 0, *lin2b = 0;
    const int *ei = 0, *batch = 0;

    for (int i = 0; i < n_in; i++) {
        int sz = in_sizes[i];
        const void* p = d_in[i];
        switch (sz) {
            case 1400000: x      = (const float*)p; break;
            case 5000000: ei     = (const int*)p; break;
            case 100000:  batch  = (const int*)p; break;
            case 448:     if (!Wrel1) Wrel1 = (const float*)p; else Wroot1 = (const float*)p; break;
            case 4096:    if (!Wrel)  Wrel  = (const float*)p; else Wroot  = (const float*)p; break;
            case 32:      if (!brel1) brel1 = (const float*)p; else lin1b  = (const float*)p; break;
            case 128:     brel   = (const float*)p; break;
            case 1024:    lin1w  = (const float*)p; break;
            case 64:      lin2w  = (const float*)p; break;
            case 2:       lin2b  = (const float*)p; break;
            default: break;
        }
    }
    float* out = (float*)d_out;

    const int TB = 256;

    // prep + CSR build
    k_prep<<<(N_NODES + TB - 1) / TB, TB>>>(x);
    k_hist<<<(N_EDGES / 4 + TB - 1) / TB, TB>>>(ei);
    k_scan<<<1, 1024>>>();
    k_fill<<<(N_EDGES + TB - 1) / TB, TB>>>(ei);

    // layer 1 -> h0
    k_conv1<<<CONV_BLOCKS, CONV_TPB>>>(Wrel1, brel1, Wroot1);

    // layers 2..5 : ping-pong h0 <-> h1
    int src_is_h0 = 1;
    for (int i = 0; i < 4; i++) {
        k_conv32<<<CONV_BLOCKS, CONV_TPB>>>(
            src_is_h0,
            Wrel  + i * HID * HID,
            brel  + i * HID,
            Wroot + i * HID * HID);
        src_is_h0 ^= 1;
    }

    // final h lives in h0
    k_pool<<<(8 * N_NODES + TB - 1) / TB, TB>>>(src_is_h0, batch);
    k_head<<<1, N_GRAPHS>>>(lin1w, lin1b, lin2w, lin2b, out);
}

// round 13
// speedup vs baseline: 1.2330x; 1.0084x over previous
#include <cuda_runtime.h>

#define N_NODES  100000
#define N_EDGES  2500000
#define N_GRAPHS 512
#define IN_DIM   14
#define HID      32

#define CONV_TPB    512
#define CONV_BLOCKS 592     // 9472 warps

// ---------------- device scratch ----------------
__device__ float4 d_x4[N_NODES * 4];        // x padded 14 -> 16 floats
__device__ float4 d_h0v[N_NODES * 8];
__device__ float4 d_h1v[N_NODES * 8];
__device__ float4 d_aggv[N_NODES * 8];      // gather output (agg rows)
__device__ float4 d_pool4[N_GRAPHS * 8];
__device__ int    d_deg[N_NODES];           // degree, then fill cursor
__device__ int    d_off[N_NODES + 1];       // CSR row offsets (by dst)
__device__ int    d_csrc[N_EDGES];          // CSR column = src node of each edge

__device__ __forceinline__ void red_add_v4(float4* p, float4 v) {
    asm volatile("red.global.add.v4.f32 [%0], {%1,%2,%3,%4};"
                 :: "l"(p), "f"(v.x), "f"(v.y), "f"(v.z), "f"(v.w)
                 : "memory");
}

// ---------------- prep: pad x, zero deg + pool ----------------
__global__ void k_prep(const float* __restrict__ x) {
    int i = blockIdx.x * blockDim.x + threadIdx.x;
    if (i < N_NODES) {
        float buf[16];
        #pragma unroll
        for (int k = 0; k < IN_DIM; k++) buf[k] = x[i * IN_DIM + k];
        buf[14] = 0.0f; buf[15] = 0.0f;
        #pragma unroll
        for (int k = 0; k < 4; k++)
            d_x4[i * 4 + k] = make_float4(buf[4*k], buf[4*k+1], buf[4*k+2], buf[4*k+3]);
        d_deg[i] = 0;
    }
    if (i < N_GRAPHS * 8) d_pool4[i] = make_float4(0.f, 0.f, 0.f, 0.f);
}

// ---------------- CSR build ----------------
__global__ void k_hist(const int* __restrict__ ei) {
    int i = blockIdx.x * blockDim.x + threadIdx.x;
    const int4* dst4 = (const int4*)(ei + N_EDGES);
    if (i < N_EDGES / 4) {
        int4 d = dst4[i];
        atomicAdd(&d_deg[d.x], 1);
        atomicAdd(&d_deg[d.y], 1);
        atomicAdd(&d_deg[d.z], 1);
        atomicAdd(&d_deg[d.w], 1);
    }
}

__global__ void k_scan() {
    const int C = (N_NODES + 1023) / 1024;  // 98
    __shared__ int sPart[1024];
    int t = threadIdx.x;
    int start = t * C;
    int sum = 0;
    for (int i = 0; i < C; i++) {
        int idx = start + i;
        if (idx < N_NODES) sum += d_deg[idx];
    }
    sPart[t] = sum;
    __syncthreads();
    for (int off = 1; off < 1024; off <<= 1) {
        int v = (t >= off) ? sPart[t - off] : 0;
        __syncthreads();
        sPart[t] += v;
        __syncthreads();
    }
    int run = (t == 0) ? 0 : sPart[t - 1];
    for (int i = 0; i < C; i++) {
        int idx = start + i;
        if (idx < N_NODES) {
            int d = d_deg[idx];
            d_off[idx] = run;
            d_deg[idx] = run;   // becomes fill cursor
            run += d;
        }
    }
    if (t == 0) d_off[N_NODES] = N_EDGES;
}

__global__ void k_fill(const int* __restrict__ ei) {
    int i = blockIdx.x * blockDim.x + threadIdx.x;
    if (i < N_EDGES) {
        int s = ei[i], d = ei[N_EDGES + i];
        int pos = atomicAdd(&d_deg[d], 1);
        d_csrc[pos] = s;
    }
}

// ---------------- layer 1 (fused, R12 style): gather + B=4 epilogue ----------------
__global__ void __launch_bounds__(CONV_TPB) k_conv1(const float* __restrict__ Wrel,
                                                    const float* __restrict__ brel,
                                                    const float* __restrict__ Wroot) {
    __shared__ float2 sWW[IN_DIM * HID];
    __shared__ __align__(16) float sAggT[16][16][4];
    __shared__ __align__(16) float sHinT[16][16][4];
    for (int k = threadIdx.x; k < IN_DIM * HID; k += blockDim.x)
        sWW[k] = make_float2(Wrel[k], Wroot[k]);
    __syncthreads();

    const float4* xp4 = d_x4;
    const float*  xp  = (const float*)d_x4;
    float* h0 = (float*)d_h0v;
    int lane = threadIdx.x & 31, w = threadIdx.x >> 5;
    float bias = brel[lane];
    int warpId = blockIdx.x * (CONV_TPB / 32) + w;
    int nWarps = gridDim.x * (CONV_TPB / 32);
    int grp = lane >> 2;
    int sub = lane & 3;

    const int NGRP = N_NODES / 4;
    for (int ng = warpId; ng < NGRP; ng += nWarps) {
        int n0 = ng * 4;
        #pragma unroll
        for (int b = 0; b < 4; b++) {
            int n = n0 + b;
            int beg = d_off[n], end = d_off[n + 1];
            float4 acc0 = make_float4(0.f,0.f,0.f,0.f);
            float4 acc1 = make_float4(0.f,0.f,0.f,0.f);
            for (int base = beg; base < end; base += 32) {
                int cnt = end - base; if (cnt > 32) cnt = 32;
                int sidx = (base + lane < end) ? d_csrc[base + lane] : 0;
                int j = 0;
                for (; j + 16 <= cnt; j += 16) {
                    int sa = __shfl_sync(0xffffffffu, sidx, j + grp);
                    int sb_ = __shfl_sync(0xffffffffu, sidx, j + 8 + grp);
                    float4 va = xp4[sa * 4 + sub];
                    float4 vb = xp4[sb_ * 4 + sub];
                    acc0.x += va.x; acc0.y += va.y; acc0.z += va.z; acc0.w += va.w;
                    acc1.x += vb.x; acc1.y += vb.y; acc1.z += vb.z; acc1.w += vb.w;
                }
                for (; j < cnt; j += 8) {
                    int s = __shfl_sync(0xffffffffu, sidx, j + grp);
                    if (j + grp < cnt) {
                        float4 v = xp4[s * 4 + sub];
                        acc0.x += v.x; acc0.y += v.y; acc0.z += v.z; acc0.w += v.w;
                    }
                }
            }
            float4 acc = make_float4(acc0.x + acc1.x, acc0.y + acc1.y,
                                     acc0.z + acc1.z, acc0.w + acc1.w);
            #pragma unroll
            for (int d = 4; d <= 16; d <<= 1) {
                acc.x += __shfl_xor_sync(0xffffffffu, acc.x, d);
                acc.y += __shfl_xor_sync(0xffffffffu, acc.y, d);
                acc.z += __shfl_xor_sync(0xffffffffu, acc.z, d);
                acc.w += __shfl_xor_sync(0xffffffffu, acc.w, d);
            }
            if (lane < 4) {
                sAggT[w][4*lane+0][b] = acc.x;
                sAggT[w][4*lane+1][b] = acc.y;
                sAggT[w][4*lane+2][b] = acc.z;
                sAggT[w][4*lane+3][b] = acc.w;
            }
            if (lane < 16) sHinT[w][lane][b] = xp[n * 16 + lane];
        }
        __syncwarp();

        const float4* aggv = (const float4*)&sAggT[w][0][0];
        const float4* hinv = (const float4*)&sHinT[w][0][0];
        float o0 = bias, o1 = bias, o2 = bias, o3 = bias;
        #pragma unroll
        for (int k = 0; k < IN_DIM; k++) {
            float2 wk = sWW[k * HID + lane];
            float4 av = aggv[k];
            float4 hv = hinv[k];
            o0 = fmaf(av.x, wk.x, fmaf(hv.x, wk.y, o0));
            o1 = fmaf(av.y, wk.x, fmaf(hv.y, wk.y, o1));
            o2 = fmaf(av.z, wk.x, fmaf(hv.z, wk.y, o2));
            o3 = fmaf(av.w, wk.x, fmaf(hv.w, wk.y, o3));
        }
        h0[(n0+0) * HID + lane] = fmaxf(o0, 0.0f);
        h0[(n0+1) * HID + lane] = fmaxf(o1, 0.0f);
        h0[(n0+2) * HID + lane] = fmaxf(o2, 0.0f);
        h0[(n0+3) * HID + lane] = fmaxf(o3, 0.0f);
        __syncwarp();
    }
}

// ---------------- layers 2..5 phase A: pure gather -> d_aggv -----------------------
__global__ void __launch_bounds__(CONV_TPB) k_gather32(int src_is_h0) {
    const float4* hin4 = src_is_h0 ? d_h0v : d_h1v;
    int lane = threadIdx.x & 31, w = threadIdx.x >> 5;
    int warpId = blockIdx.x * (CONV_TPB / 32) + w;
    int nWarps = gridDim.x * (CONV_TPB / 32);
    int grp = lane >> 3;     // 0..3: edge within 4-edge batch
    int sub = lane & 7;      // 0..7: float4 within 32-float row

    for (int n = warpId; n < N_NODES; n += nWarps) {
        int beg = d_off[n], end = d_off[n + 1];
        float4 acc0 = make_float4(0.f,0.f,0.f,0.f);
        float4 acc1 = make_float4(0.f,0.f,0.f,0.f);
        for (int base = beg; base < end; base += 32) {
            int cnt = end - base; if (cnt > 32) cnt = 32;
            int sidx = (base + lane < end) ? d_csrc[base + lane] : 0;
            int j = 0;
            for (; j + 8 <= cnt; j += 8) {
                int sa = __shfl_sync(0xffffffffu, sidx, j + grp);
                int sb_ = __shfl_sync(0xffffffffu, sidx, j + 4 + grp);
                float4 va = hin4[sa * 8 + sub];
                float4 vb = hin4[sb_ * 8 + sub];
                acc0.x += va.x; acc0.y += va.y; acc0.z += va.z; acc0.w += va.w;
                acc1.x += vb.x; acc1.y += vb.y; acc1.z += vb.z; acc1.w += vb.w;
            }
            for (; j < cnt; j += 4) {
                int s = __shfl_sync(0xffffffffu, sidx, j + grp);
                if (j + grp < cnt) {
                    float4 v = hin4[s * 8 + sub];
                    acc0.x += v.x; acc0.y += v.y; acc0.z += v.z; acc0.w += v.w;
                }
            }
        }
        float4 acc = make_float4(acc0.x + acc1.x, acc0.y + acc1.y,
                                 acc0.z + acc1.z, acc0.w + acc1.w);
        #pragma unroll
        for (int d = 8; d <= 16; d <<= 1) {
            acc.x += __shfl_xor_sync(0xffffffffu, acc.x, d);
            acc.y += __shfl_xor_sync(0xffffffffu, acc.y, d);
            acc.z += __shfl_xor_sync(0xffffffffu, acc.z, d);
            acc.w += __shfl_xor_sync(0xffffffffu, acc.w, d);
        }
        if (lane < 8) d_aggv[n * 8 + lane] = acc;
    }
}

// ---------------- layers 2..5 phase B: dense update (streaming GEMM-ish) -----------
// warp -> 4 nodes. Loads agg+hin rows coalesced, transposes via smem, B=4 epilogue.
#define UPD_TPB 256
__global__ void __launch_bounds__(UPD_TPB) k_update32(int src_is_h0,
                                                      const float* __restrict__ Wrel,
                                                      const float* __restrict__ brel,
                                                      const float* __restrict__ Wroot) {
    __shared__ float2 sWW[HID * HID];                    // 8 KB
    __shared__ __align__(16) float sAggT[8][HID][4];     // 4 KB
    __shared__ __align__(16) float sHinT[8][HID][4];     // 4 KB
    for (int k = threadIdx.x; k < HID * HID; k += blockDim.x)
        sWW[k] = make_float2(Wrel[k], Wroot[k]);
    __syncthreads();

    const float* agg = (const float*)d_aggv;
    const float* hin = src_is_h0 ? (const float*)d_h0v : (const float*)d_h1v;
    float*      hout = src_is_h0 ? (float*)d_h1v       : (float*)d_h0v;

    int lane = threadIdx.x & 31, w = threadIdx.x >> 5;
    float bias = brel[lane];
    int warpId = blockIdx.x * (UPD_TPB / 32) + w;
    if (warpId >= N_NODES / 4) return;
    int n0 = warpId * 4;

    // coalesced row loads, transposed store: sT[k][b] = row[n0+b][k], k = lane
    #pragma unroll
    for (int b = 0; b < 4; b++) {
        sAggT[w][lane][b] = agg[(n0 + b) * HID + lane];
        sHinT[w][lane][b] = hin[(n0 + b) * HID + lane];
    }
    __syncwarp();

    const float4* aggv = (const float4*)&sAggT[w][0][0];
    const float4* hinv = (const float4*)&sHinT[w][0][0];
    float o0 = bias, o1 = bias, o2 = bias, o3 = bias;
    #pragma unroll
    for (int k = 0; k < HID; k++) {
        float2 wk = sWW[k * HID + lane];
        float4 av = aggv[k];
        float4 hv = hinv[k];
        o0 = fmaf(av.x, wk.x, fmaf(hv.x, wk.y, o0));
        o1 = fmaf(av.y, wk.x, fmaf(hv.y, wk.y, o1));
        o2 = fmaf(av.z, wk.x, fmaf(hv.z, wk.y, o2));
        o3 = fmaf(av.w, wk.x, fmaf(hv.w, wk.y, o3));
    }
    hout[(n0+0) * HID + lane] = fmaxf(o0, 0.0f);
    hout[(n0+1) * HID + lane] = fmaxf(o1, 0.0f);
    hout[(n0+2) * HID + lane] = fmaxf(o2, 0.0f);
    hout[(n0+3) * HID + lane] = fmaxf(o3, 0.0f);
}

// ---------------- sum-pool per graph ----------------
__global__ void k_pool(int src_is_h0, const int* __restrict__ batch) {
    int t = blockIdx.x * blockDim.x + threadIdx.x;
    if (t >= 8 * N_NODES) return;
    const float4* h = src_is_h0 ? d_h0v : d_h1v;
    int n = t >> 3, c = t & 7;
    int g = batch[n];
    float4 v = h[n * 8 + c];
    red_add_v4(&d_pool4[g * 8 + c], v);
}

// ---------------- MLP head + log_softmax ----------------
__global__ void k_head(const float* __restrict__ lin1w, const float* __restrict__ lin1b,
                       const float* __restrict__ lin2w, const float* __restrict__ lin2b,
                       float* __restrict__ out) {
    __shared__ float s1[HID * HID], sb1[HID], s2[HID * 2], sb2[2];
    for (int k = threadIdx.x; k < HID * HID; k += blockDim.x) s1[k] = lin1w[k];
    if (threadIdx.x < HID)     sb1[threadIdx.x] = lin1b[threadIdx.x];
    if (threadIdx.x < HID * 2) s2[threadIdx.x]  = lin2w[threadIdx.x];
    if (threadIdx.x < 2)       sb2[threadIdx.x] = lin2b[threadIdx.x];
    __syncthreads();

    int g = threadIdx.x;
    if (g >= N_GRAPHS) return;

    const float* pool = (const float*)d_pool4;
    float gr[HID];
    #pragma unroll
    for (int k = 0; k < HID; k++) gr[k] = pool[g * HID + k];

    float hid[HID];
    for (int j = 0; j < HID; j++) {
        float acc = sb1[j];
        #pragma unroll
        for (int k = 0; k < HID; k++) acc += gr[k] * s1[k * HID + j];
        hid[j] = fmaxf(acc, 0.0f);
    }
    float l0 = sb2[0], l1 = sb2[1];
    #pragma unroll
    for (int k = 0; k < HID; k++) {
        l0 += hid[k] * s2[k * 2 + 0];
        l1 += hid[k] * s2[k * 2 + 1];
    }
    float m   = fmaxf(l0, l1);
    float lse = m + logf(expf(l0 - m) + expf(l1 - m));
    out[g * 2 + 0] = l0 - lse;
    out[g * 2 + 1] = l1 - lse;
}

// ---------------- launch: inputs identified BY ELEMENT COUNT (order-agnostic) -------
extern "C" void kernel_launch(void* const* d_in, const int* in_sizes, int n_in,
                              void* d_out, int out_size) {
    const float *x = 0, *Wrel1 = 0, *brel1 = 0, *Wroot1 = 0;
    const float *Wrel = 0, *brel = 0, *Wroot = 0;
    const float *lin1w = 0, *lin1b = 0, *lin2w = 0, *lin2b = 0;
    const int *ei = 0, *batch = 0;

    for (int i = 0; i < n_in; i++) {
        int sz = in_sizes[i];
        const void* p = d_in[i];
        switch (sz) {
            case 1400000: x      = (const float*)p; break;
            case 5000000: ei     = (const int*)p; break;
            case 100000:  batch  = (const int*)p; break;
            case 448:     if (!Wrel1) Wrel1 = (const float*)p; else Wroot1 = (const float*)p; break;
            case 4096:    if (!Wrel)  Wrel  = (const float*)p; else Wroot  = (const float*)p; break;
            case 32:      if (!brel1) brel1 = (const float*)p; else lin1b  = (const float*)p; break;
            case 128:     brel   = (const float*)p; break;
            case 1024:    lin1w  = (const float*)p; break;
            case 64:      lin2w  = (const float*)p; break;
            case 2:       lin2b  = (const float*)p; break;
            default: break;
        }
    }
    float* out = (float*)d_out;

    const int TB = 256;

    // prep + CSR build
    k_prep<<<(N_NODES + TB - 1) / TB, TB>>>(x);
    k_hist<<<(N_EDGES / 4 + TB - 1) / TB, TB>>>(ei);
    k_scan<<<1, 1024>>>();
    k_fill<<<(N_EDGES + TB - 1) / TB, TB>>>(ei);

    // layer 1 -> h0 (fused)
    k_conv1<<<CONV_BLOCKS, CONV_TPB>>>(Wrel1, brel1, Wroot1);

    // layers 2..5 : split gather / update, ping-pong h0 <-> h1
    const int UPD_BLOCKS = (N_NODES / 4 + (UPD_TPB / 32) - 1) / (UPD_TPB / 32);
    int src_is_h0 = 1;
    for (int i = 0; i < 4; i++) {
        k_gather32<<<CONV_BLOCKS, CONV_TPB>>>(src_is_h0);
        k_update32<<<UPD_BLOCKS, UPD_TPB>>>(
            src_is_h0,
            Wrel  + i * HID * HID,
            brel  + i * HID,
            Wroot + i * HID * HID);
        src_is_h0 ^= 1;
    }

    // final h lives in h0
    k_pool<<<(8 * N_NODES + TB - 1) / TB, TB>>>(src_is_h0, batch);
    k_head<<<1, N_GRAPHS>>>(lin1w, lin1b, lin2w, lin2b, out);
}